// round 2
// baseline (speedup 1.0000x reference)
#include <cuda_runtime.h>
#include <cuda_bf16.h>
#include <cstdint>

// Problem constants
#define B_DIM 32
#define N_DIM 2048
#define L_DIM 128
#define D_DIM 1024

// Tiling
#define TILE_M   128
#define K_CHUNK  64                  // bf16 elems per chunk row = 128 bytes
#define N_CHUNKS (D_DIM / K_CHUNK)   // 16

__device__ int g_tok_is64;

static __device__ __forceinline__ uint32_t smem_u32(const void* p) {
    uint32_t a;
    asm("{ .reg .u64 t; cvta.to.shared.u64 t, %1; cvt.u32.u64 %0, t; }"
        : "=r"(a) : "l"(p));
    return a;
}

static __device__ __forceinline__ uint32_t sw128(uint32_t off) {
    return off ^ ((off >> 3) & 0x70u);
}

static __device__ __forceinline__ void ldmatrix_x4(uint32_t& r0, uint32_t& r1,
                                                   uint32_t& r2, uint32_t& r3,
                                                   uint32_t addr) {
    asm volatile("ldmatrix.sync.aligned.m8n8.x4.shared.b16 {%0,%1,%2,%3}, [%4];"
                 : "=r"(r0), "=r"(r1), "=r"(r2), "=r"(r3) : "r"(addr));
}

static __device__ __forceinline__ void mma16816(float* c, uint32_t a0, uint32_t a1,
                                                uint32_t a2, uint32_t a3,
                                                uint32_t b0, uint32_t b1) {
    asm volatile(
        "mma.sync.aligned.m16n8k16.row.col.f32.bf16.bf16.f32 "
        "{%0,%1,%2,%3}, {%4,%5,%6,%7}, {%8,%9}, {%0,%1,%2,%3};"
        : "+f"(c[0]), "+f"(c[1]), "+f"(c[2]), "+f"(c[3])
        : "r"(a0), "r"(a1), "r"(a2), "r"(a3), "r"(b0), "r"(b1));
}

// ---------------- prep: zero output + detect token dtype ----------------
// token_ids is int64 in the reference, but if JAX x64 is disabled it becomes
// int32. Detect by scanning high words of the first B*L/2 8-byte slots
// (in-bounds under both interpretations): valid int64 tokens < 32000 have
// hi == 0 everywhere.
__global__ void prep_kernel(const uint2* __restrict__ tok_raw, float* __restrict__ out) {
    __shared__ int any_hi;
    if (threadIdx.x == 0) { any_hi = 0; out[0] = 0.0f; }
    __syncthreads();
    int local = 0;
    for (int i = threadIdx.x; i < (B_DIM * L_DIM) / 2; i += blockDim.x) {
        if (tok_raw[i].y != 0u) local = 1;
    }
    if (local) any_hi = 1;   // benign race
    __syncthreads();
    if (threadIdx.x == 0) g_tok_is64 = any_hi ? 0 : 1;
}

// ---------------- main fused kernel ----------------
__global__ void __launch_bounds__(256, 2)
captioner_kernel(const float* __restrict__ X,      // [B, N, D]
                 const void*  __restrict__ tok,    // [B, L] i64 or i32
                 const float* __restrict__ E,      // [V, D]
                 float* __restrict__ out)
{
    __shared__ __align__(1024) uint8_t sA[TILE_M * 128];   // 16 KB bf16, SW128
    __shared__ __align__(1024) uint8_t sB[L_DIM * 128];    // 16 KB
    __shared__ float x2s[TILE_M];
    __shared__ float y2s[L_DIM];
    __shared__ float minw[TILE_M][2];
    __shared__ long long toks[L_DIM];
    __shared__ float wsum[8];

    const int tid  = threadIdx.x;
    const int wid  = tid >> 5;
    const int lid  = tid & 31;
    const int b    = blockIdx.y;
    const int tile = blockIdx.x;

    // token gather
    if (tid < L_DIM) {
        long long idx;
        if (g_tok_is64) idx = ((const long long*)tok)[(size_t)b * L_DIM + tid];
        else            idx = (long long)((const int*)tok)[b * L_DIM + tid];
        toks[tid] = idx;
    }
    __syncthreads();

    // ---- loader mapping: 16 threads per row, 8 rows/thread/chunk ----
    const int rbase = tid >> 4;      // 0..15
    const int c4    = tid & 15;      // float4 column within 64-float chunk
    float x2p[8], y2p[8];
    #pragma unroll
    for (int i = 0; i < 8; i++) { x2p[i] = 0.0f; y2p[i] = 0.0f; }

    const float4* __restrict__ Xv = (const float4*)X;
    const float4* __restrict__ Ev = (const float4*)E;
    const size_t xrow0 = (size_t)b * N_DIM + (size_t)tile * TILE_M;

    const uint32_t sAu = smem_u32(sA);
    const uint32_t sBu = smem_u32(sB);

    // ---- mma warp tiling: 4 (M) x 2 (N) warps ----
    const int wid_m = wid >> 1;          // 0..3 -> 32 rows each
    const int wid_n = wid & 1;           // 0..1 -> 64 cols each
    const int g  = lid >> 2;             // accum row group
    const int t4 = lid & 3;
    const int lm = lid >> 3;             // ldmatrix matrix index 0..3
    const int lr = lid & 7;              // row within 8x8 matrix

    float acc[2][8][4];
    #pragma unroll
    for (int mt = 0; mt < 2; mt++)
        #pragma unroll
        for (int j = 0; j < 8; j++)
            #pragma unroll
            for (int q = 0; q < 4; q++) acc[mt][j][q] = 0.0f;

    // precomputed ldmatrix lane row/byte offsets (without kk term)
    // A: row = wid_m*32 + mt*16 + (lm&1)*8 + lr ; kbyte += (lm>>1)*16
    // B: row = wid_n*64 + np*16 + (lm>>1)*8 + lr ; kbyte += (lm&1)*16
    const uint32_t aRow0 = (uint32_t)(wid_m * 32 + (lm & 1) * 8 + lr) * 128 + (lm >> 1) * 16;
    const uint32_t bRow0 = (uint32_t)(wid_n * 64 + (lm >> 1) * 8 + lr) * 128 + (lm & 1) * 16;

    for (int ck = 0; ck < N_CHUNKS; ck++) {
        const int kofs4 = ck * (K_CHUNK / 4) + c4;
        #pragma unroll
        for (int it = 0; it < 8; it++) {
            const int row = rbase + it * 16;

            float4 f = __ldg(&Xv[(xrow0 + row) * (D_DIM / 4) + kofs4]);
            x2p[it] += f.x * f.x + f.y * f.y + f.z * f.z + f.w * f.w;
            __nv_bfloat162 a0 = __floats2bfloat162_rn(f.x, f.y);
            __nv_bfloat162 a1 = __floats2bfloat162_rn(f.z, f.w);
            uint32_t off = (uint32_t)(row * 128 + c4 * 8);
            uint32_t sw  = sw128(off);
            uint2 va; va.x = *(const uint32_t*)&a0; va.y = *(const uint32_t*)&a1;
            *(uint2*)(sA + sw) = va;

            const long long e = toks[row];
            float4 gg = __ldg(&Ev[(size_t)e * (D_DIM / 4) + kofs4]);
            y2p[it] += gg.x * gg.x + gg.y * gg.y + gg.z * gg.z + gg.w * gg.w;
            __nv_bfloat162 b0 = __floats2bfloat162_rn(gg.x, gg.y);
            __nv_bfloat162 b1 = __floats2bfloat162_rn(gg.z, gg.w);
            uint2 vb; vb.x = *(const uint32_t*)&b0; vb.y = *(const uint32_t*)&b1;
            *(uint2*)(sB + sw) = vb;
        }
        __syncthreads();

        // ---- compute: 4 k-steps of 16 over this 64-wide chunk ----
        #pragma unroll
        for (int kk = 0; kk < 4; kk++) {
            const uint32_t kb = (uint32_t)kk * 32;
            uint32_t a[2][4];
            #pragma unroll
            for (int mt = 0; mt < 2; mt++) {
                uint32_t off = aRow0 + (uint32_t)mt * (16 * 128) + kb;
                ldmatrix_x4(a[mt][0], a[mt][1], a[mt][2], a[mt][3], sAu + sw128(off));
            }
            #pragma unroll
            for (int np = 0; np < 4; np++) {
                uint32_t off = bRow0 + (uint32_t)np * (16 * 128) + kb;
                uint32_t b0, b1, b2, b3;
                ldmatrix_x4(b0, b1, b2, b3, sBu + sw128(off));
                #pragma unroll
                for (int mt = 0; mt < 2; mt++) {
                    mma16816(acc[mt][2 * np],     a[mt][0], a[mt][1], a[mt][2], a[mt][3], b0, b1);
                    mma16816(acc[mt][2 * np + 1], a[mt][0], a[mt][1], a[mt][2], a[mt][3], b2, b3);
                }
            }
        }
        __syncthreads();
    }

    // ---- reduce per-row squared norms (16 lanes per row, same warp) ----
    #pragma unroll
    for (int it = 0; it < 8; it++) {
        float vx = x2p[it], vy = y2p[it];
        #pragma unroll
        for (int o = 1; o < 16; o <<= 1) {
            vx += __shfl_xor_sync(0xFFFFFFFFu, vx, o);
            vy += __shfl_xor_sync(0xFFFFFFFFu, vy, o);
        }
        if (c4 == 0) {
            x2s[rbase + it * 16] = vx;
            y2s[rbase + it * 16] = vy;
        }
    }
    __syncthreads();

    // ---- epilogue: q = y2[col] - 2*S, min over cols ----
    float minq[2][2];
    minq[0][0] = minq[0][1] = minq[1][0] = minq[1][1] = 3.4e38f;
    #pragma unroll
    for (int mt = 0; mt < 2; mt++) {
        #pragma unroll
        for (int j = 0; j < 8; j++) {
            const int col = wid_n * 64 + j * 8 + t4 * 2;
            const float y0 = y2s[col], y1 = y2s[col + 1];
            minq[mt][0] = fminf(minq[mt][0],
                                fminf(y0 - 2.0f * acc[mt][j][0], y1 - 2.0f * acc[mt][j][1]));
            minq[mt][1] = fminf(minq[mt][1],
                                fminf(y0 - 2.0f * acc[mt][j][2], y1 - 2.0f * acc[mt][j][3]));
        }
    }
    // min across the 4 lanes sharing the same rows (t4 = lane&3)
    #pragma unroll
    for (int mt = 0; mt < 2; mt++) {
        #pragma unroll
        for (int h = 0; h < 2; h++) {
            float v = minq[mt][h];
            v = fminf(v, __shfl_xor_sync(0xFFFFFFFFu, v, 1));
            v = fminf(v, __shfl_xor_sync(0xFFFFFFFFu, v, 2));
            minq[mt][h] = v;
        }
    }
    if (t4 == 0) {
        #pragma unroll
        for (int mt = 0; mt < 2; mt++) {
            const int r = wid_m * 32 + mt * 16 + g;
            minw[r][wid_n]     = minq[mt][0];
            minw[r + 8][wid_n] = minq[mt][1];
        }
    }
    __syncthreads();

    // combine the two warp-column halves, sqrt, sum
    float dist = 0.0f;
    if (tid < TILE_M) {
        const float m = fminf(minw[tid][0], minw[tid][1]);
        dist = sqrtf(fmaxf(x2s[tid] + m, 0.0f));
    }
    #pragma unroll
    for (int o = 16; o >= 1; o >>= 1)
        dist += __shfl_xor_sync(0xFFFFFFFFu, dist, o);
    if (lid == 0) wsum[wid] = dist;
    __syncthreads();

    if (tid == 0) {
        float s = (wsum[0] + wsum[1] + wsum[2] + wsum[3]) *
                  (1.0f / ((float)B_DIM * (float)N_DIM));
        atomicAdd(out, s);
    }
}

// ---------------- launch ----------------
extern "C" void kernel_launch(void* const* d_in, const int* in_sizes, int n_in,
                              void* d_out, int out_size) {
    const float* X   = (const float*)d_in[0];
    const void*  tok = d_in[1];
    const float* E   = (const float*)d_in[2];
    float* out = (float*)d_out;

    prep_kernel<<<1, 256>>>((const uint2*)tok, out);
    dim3 grid(N_DIM / TILE_M, B_DIM);   // (16, 32)
    captioner_kernel<<<grid, 256>>>(X, tok, E, out);
}

// round 3
// speedup vs baseline: 2.3147x; 2.3147x over previous
#include <cuda_runtime.h>
#include <cuda_bf16.h>
#include <cstdint>

// Problem constants
#define B_DIM 32
#define N_DIM 2048
#define L_DIM 128
#define D_DIM 1024

// Tiling
#define TILE_M   128
#define K_CHUNK  64                  // bf16 elems per chunk row = 128 bytes
#define N_CHUNKS (D_DIM / K_CHUNK)   // 16

__device__ int g_tok_is64;

static __device__ __forceinline__ uint32_t smem_u32(const void* p) {
    uint32_t a;
    asm("{ .reg .u64 t; cvta.to.shared.u64 t, %1; cvt.u32.u64 %0, t; }"
        : "=r"(a) : "l"(p));
    return a;
}

static __device__ __forceinline__ uint32_t sw128(uint32_t off) {
    return off ^ ((off >> 3) & 0x70u);
}

static __device__ __forceinline__ void ldmatrix_x4(uint32_t& r0, uint32_t& r1,
                                                   uint32_t& r2, uint32_t& r3,
                                                   uint32_t addr) {
    asm volatile("ldmatrix.sync.aligned.m8n8.x4.shared.b16 {%0,%1,%2,%3}, [%4];"
                 : "=r"(r0), "=r"(r1), "=r"(r2), "=r"(r3) : "r"(addr));
}

static __device__ __forceinline__ void mma16816(float* c, uint32_t a0, uint32_t a1,
                                                uint32_t a2, uint32_t a3,
                                                uint32_t b0, uint32_t b1) {
    asm volatile(
        "mma.sync.aligned.m16n8k16.row.col.f32.bf16.bf16.f32 "
        "{%0,%1,%2,%3}, {%4,%5,%6,%7}, {%8,%9}, {%0,%1,%2,%3};"
        : "+f"(c[0]), "+f"(c[1]), "+f"(c[2]), "+f"(c[3])
        : "r"(a0), "r"(a1), "r"(a2), "r"(a3), "r"(b0), "r"(b1));
}

// ---------------- prep: zero output + detect token dtype ----------------
__global__ void prep_kernel(const uint2* __restrict__ tok_raw, float* __restrict__ out) {
    __shared__ int any_hi;
    if (threadIdx.x == 0) { any_hi = 0; out[0] = 0.0f; }
    __syncthreads();
    int local = 0;
    for (int i = threadIdx.x; i < (B_DIM * L_DIM) / 2; i += blockDim.x) {
        if (tok_raw[i].y != 0u) local = 1;
    }
    if (local) any_hi = 1;   // benign race
    __syncthreads();
    if (threadIdx.x == 0) g_tok_is64 = any_hi ? 0 : 1;
}

// ---------------- main fused kernel ----------------
__global__ void __launch_bounds__(256)
captioner_kernel(const float* __restrict__ X,      // [B, N, D]
                 const void*  __restrict__ tok,    // [B, L] i64 or i32
                 const float* __restrict__ E,      // [V, D]
                 float* __restrict__ out)
{
    // double-buffered bf16 tiles, SW128-swizzled
    __shared__ __align__(1024) uint8_t sA[2][TILE_M * 128];   // 2 x 16 KB
    __shared__ __align__(1024) uint8_t sB[2][L_DIM * 128];    // 2 x 16 KB
    __shared__ float x2s[TILE_M];
    __shared__ float y2s[L_DIM];
    __shared__ float minw[TILE_M][2];
    __shared__ long long toks[L_DIM];
    __shared__ float wsum[8];

    const int tid  = threadIdx.x;
    const int wid  = tid >> 5;
    const int lid  = tid & 31;
    const int b    = blockIdx.y;
    const int tile = blockIdx.x;

    // token gather
    if (tid < L_DIM) {
        long long idx;
        if (g_tok_is64) idx = ((const long long*)tok)[(size_t)b * L_DIM + tid];
        else            idx = (long long)((const int*)tok)[b * L_DIM + tid];
        toks[tid] = idx;
    }
    __syncthreads();

    // ---- loader mapping: 16 threads per row, 8 rows/thread/chunk ----
    const int rbase = tid >> 4;      // 0..15
    const int c4    = tid & 15;      // float4 column within 64-float chunk
    float x2p[8], y2p[8];
    #pragma unroll
    for (int i = 0; i < 8; i++) { x2p[i] = 0.0f; y2p[i] = 0.0f; }

    const float4* __restrict__ Xv = (const float4*)X;
    const float4* __restrict__ Ev = (const float4*)E;
    const size_t xrow0 = (size_t)b * N_DIM + (size_t)tile * TILE_M;

    const uint32_t sAu = smem_u32(&sA[0][0]);
    const uint32_t sBu = smem_u32(&sB[0][0]);

    // per-thread swizzled store offset within a tile (row-major 128B rows)
    uint32_t st_off[8];
    #pragma unroll
    for (int it = 0; it < 8; it++) {
        uint32_t off = (uint32_t)((rbase + it * 16) * 128 + c4 * 8);
        st_off[it] = sw128(off);
    }

    // ---- mma warp tiling: 4 (M) x 2 (N) warps ----
    const int wid_m = wid >> 1;          // 0..3 -> 32 rows each
    const int wid_n = wid & 1;           // 0..1 -> 64 cols each
    const int g  = lid >> 2;             // accum row group
    const int t4 = lid & 3;
    const int lm = lid >> 3;             // ldmatrix matrix index 0..3
    const int lr = lid & 7;              // row within 8x8 matrix

    float acc[2][8][4];
    #pragma unroll
    for (int mt = 0; mt < 2; mt++)
        #pragma unroll
        for (int j = 0; j < 8; j++)
            #pragma unroll
            for (int q = 0; q < 4; q++) acc[mt][j][q] = 0.0f;

    const uint32_t aRow0 = (uint32_t)(wid_m * 32 + (lm & 1) * 8 + lr) * 128 + (lm >> 1) * 16;
    const uint32_t bRow0 = (uint32_t)(wid_n * 64 + (lm >> 1) * 8 + lr) * 128 + (lm & 1) * 16;

    // ---- pipeline: register-staged prefetch + double-buffered SMEM ----
    float4 fa[8], fb[8];

    // prologue: load chunk 0
    {
        const int kofs4 = c4;   // ck = 0
        #pragma unroll
        for (int it = 0; it < 8; it++) {
            const int row = rbase + it * 16;
            fa[it] = __ldg(&Xv[(xrow0 + row) * (D_DIM / 4) + kofs4]);
            fb[it] = __ldg(&Ev[(size_t)toks[row] * (D_DIM / 4) + kofs4]);
        }
    }

    for (int ck = 0; ck < N_CHUNKS; ck++) {
        const int buf = ck & 1;
        uint8_t* __restrict__ tA = sA[buf];
        uint8_t* __restrict__ tB = sB[buf];

        // ---- convert + swizzle-store current chunk, accumulate norms ----
        #pragma unroll
        for (int it = 0; it < 8; it++) {
            const float4 f = fa[it];
            x2p[it] += f.x * f.x + f.y * f.y + f.z * f.z + f.w * f.w;
            __nv_bfloat162 a0 = __floats2bfloat162_rn(f.x, f.y);
            __nv_bfloat162 a1 = __floats2bfloat162_rn(f.z, f.w);
            uint2 va; va.x = *(const uint32_t*)&a0; va.y = *(const uint32_t*)&a1;
            *(uint2*)(tA + st_off[it]) = va;

            const float4 gg = fb[it];
            y2p[it] += gg.x * gg.x + gg.y * gg.y + gg.z * gg.z + gg.w * gg.w;
            __nv_bfloat162 b0 = __floats2bfloat162_rn(gg.x, gg.y);
            __nv_bfloat162 b1 = __floats2bfloat162_rn(gg.z, gg.w);
            uint2 vb; vb.x = *(const uint32_t*)&b0; vb.y = *(const uint32_t*)&b1;
            *(uint2*)(tB + st_off[it]) = vb;
        }
        __syncthreads();

        // ---- prefetch next chunk (latency hidden under the MMA section) ----
        if (ck + 1 < N_CHUNKS) {
            const int kofs4 = (ck + 1) * (K_CHUNK / 4) + c4;
            #pragma unroll
            for (int it = 0; it < 8; it++) {
                const int row = rbase + it * 16;
                fa[it] = __ldg(&Xv[(xrow0 + row) * (D_DIM / 4) + kofs4]);
                fb[it] = __ldg(&Ev[(size_t)toks[row] * (D_DIM / 4) + kofs4]);
            }
        }

        // ---- compute: 4 k-steps of 16 over this 64-wide chunk ----
        const uint32_t baseA = sAu + (uint32_t)buf * (TILE_M * 128);
        const uint32_t baseB = sBu + (uint32_t)buf * (L_DIM * 128);
        #pragma unroll
        for (int kk = 0; kk < 4; kk++) {
            const uint32_t kb = (uint32_t)kk * 32;
            uint32_t a[2][4];
            #pragma unroll
            for (int mt = 0; mt < 2; mt++) {
                uint32_t off = aRow0 + (uint32_t)mt * (16 * 128) + kb;
                ldmatrix_x4(a[mt][0], a[mt][1], a[mt][2], a[mt][3], baseA + sw128(off));
            }
            #pragma unroll
            for (int np = 0; np < 4; np++) {
                uint32_t off = bRow0 + (uint32_t)np * (16 * 128) + kb;
                uint32_t b0, b1, b2, b3;
                ldmatrix_x4(b0, b1, b2, b3, baseB + sw128(off));
                #pragma unroll
                for (int mt = 0; mt < 2; mt++) {
                    mma16816(acc[mt][2 * np],     a[mt][0], a[mt][1], a[mt][2], a[mt][3], b0, b1);
                    mma16816(acc[mt][2 * np + 1], a[mt][0], a[mt][1], a[mt][2], a[mt][3], b2, b3);
                }
            }
        }
        // no trailing sync: tile[buf] is next overwritten in iter ck+2,
        // whose store is gated by sync(ck+1), which every warp reaches only
        // after finishing its MMA(ck).
    }

    // ---- reduce per-row squared norms (16 lanes per row, same warp) ----
    #pragma unroll
    for (int it = 0; it < 8; it++) {
        float vx = x2p[it], vy = y2p[it];
        #pragma unroll
        for (int o = 1; o < 16; o <<= 1) {
            vx += __shfl_xor_sync(0xFFFFFFFFu, vx, o);
            vy += __shfl_xor_sync(0xFFFFFFFFu, vy, o);
        }
        if (c4 == 0) {
            x2s[rbase + it * 16] = vx;
            y2s[rbase + it * 16] = vy;
        }
    }
    __syncthreads();

    // ---- epilogue: q = y2[col] - 2*S, min over cols ----
    float minq[2][2];
    minq[0][0] = minq[0][1] = minq[1][0] = minq[1][1] = 3.4e38f;
    #pragma unroll
    for (int mt = 0; mt < 2; mt++) {
        #pragma unroll
        for (int j = 0; j < 8; j++) {
            const int col = wid_n * 64 + j * 8 + t4 * 2;
            const float y0 = y2s[col], y1 = y2s[col + 1];
            minq[mt][0] = fminf(minq[mt][0],
                                fminf(y0 - 2.0f * acc[mt][j][0], y1 - 2.0f * acc[mt][j][1]));
            minq[mt][1] = fminf(minq[mt][1],
                                fminf(y0 - 2.0f * acc[mt][j][2], y1 - 2.0f * acc[mt][j][3]));
        }
    }
    #pragma unroll
    for (int mt = 0; mt < 2; mt++) {
        #pragma unroll
        for (int h = 0; h < 2; h++) {
            float v = minq[mt][h];
            v = fminf(v, __shfl_xor_sync(0xFFFFFFFFu, v, 1));
            v = fminf(v, __shfl_xor_sync(0xFFFFFFFFu, v, 2));
            minq[mt][h] = v;
        }
    }
    if (t4 == 0) {
        #pragma unroll
        for (int mt = 0; mt < 2; mt++) {
            const int r = wid_m * 32 + mt * 16 + g;
            minw[r][wid_n]     = minq[mt][0];
            minw[r + 8][wid_n] = minq[mt][1];
        }
    }
    __syncthreads();

    float dist = 0.0f;
    if (tid < TILE_M) {
        const float m = fminf(minw[tid][0], minw[tid][1]);
        dist = sqrtf(fmaxf(x2s[tid] + m, 0.0f));
    }
    #pragma unroll
    for (int o = 16; o >= 1; o >>= 1)
        dist += __shfl_xor_sync(0xFFFFFFFFu, dist, o);
    if (lid == 0) wsum[wid] = dist;
    __syncthreads();

    if (tid == 0) {
        float s = (wsum[0] + wsum[1] + wsum[2] + wsum[3]) *
                  (1.0f / ((float)B_DIM * (float)N_DIM));
        atomicAdd(out, s);
    }
}

// ---------------- launch ----------------
extern "C" void kernel_launch(void* const* d_in, const int* in_sizes, int n_in,
                              void* d_out, int out_size) {
    const float* X   = (const float*)d_in[0];
    const void*  tok = d_in[1];
    const float* E   = (const float*)d_in[2];
    float* out = (float*)d_out;

    prep_kernel<<<1, 256>>>((const uint2*)tok, out);
    dim3 grid(N_DIM / TILE_M, B_DIM);   // (16, 32)
    captioner_kernel<<<grid, 256>>>(X, tok, E, out);
}

// round 4
// speedup vs baseline: 2.3564x; 1.0180x over previous
#include <cuda_runtime.h>
#include <cuda_bf16.h>
#include <cstdint>

// Problem constants
#define B_DIM 32
#define N_DIM 2048
#define L_DIM 128
#define D_DIM 1024

// Tiling
#define TILE_M   64
#define K_CHUNK  64                  // bf16 elems per chunk row = 128 bytes
#define N_CHUNKS (D_DIM / K_CHUNK)   // 16

__device__ int g_tok_is64;

static __device__ __forceinline__ uint32_t smem_u32(const void* p) {
    uint32_t a;
    asm("{ .reg .u64 t; cvta.to.shared.u64 t, %1; cvt.u32.u64 %0, t; }"
        : "=r"(a) : "l"(p));
    return a;
}

static __device__ __forceinline__ uint32_t sw128(uint32_t off) {
    return off ^ ((off >> 3) & 0x70u);
}

static __device__ __forceinline__ void ldmatrix_x4(uint32_t& r0, uint32_t& r1,
                                                   uint32_t& r2, uint32_t& r3,
                                                   uint32_t addr) {
    asm volatile("ldmatrix.sync.aligned.m8n8.x4.shared.b16 {%0,%1,%2,%3}, [%4];"
                 : "=r"(r0), "=r"(r1), "=r"(r2), "=r"(r3) : "r"(addr));
}

static __device__ __forceinline__ void mma16816(float* c, uint32_t a0, uint32_t a1,
                                                uint32_t a2, uint32_t a3,
                                                uint32_t b0, uint32_t b1) {
    asm volatile(
        "mma.sync.aligned.m16n8k16.row.col.f32.bf16.bf16.f32 "
        "{%0,%1,%2,%3}, {%4,%5,%6,%7}, {%8,%9}, {%0,%1,%2,%3};"
        : "+f"(c[0]), "+f"(c[1]), "+f"(c[2]), "+f"(c[3])
        : "r"(a0), "r"(a1), "r"(a2), "r"(a3), "r"(b0), "r"(b1));
}

// ---------------- prep: zero output + detect token dtype ----------------
__global__ void prep_kernel(const uint2* __restrict__ tok_raw, float* __restrict__ out) {
    __shared__ int any_hi;
    if (threadIdx.x == 0) { any_hi = 0; out[0] = 0.0f; }
    __syncthreads();
    int local = 0;
    for (int i = threadIdx.x; i < (B_DIM * L_DIM) / 2; i += blockDim.x) {
        if (tok_raw[i].y != 0u) local = 1;
    }
    if (local) any_hi = 1;   // benign race
    __syncthreads();
    if (threadIdx.x == 0) g_tok_is64 = any_hi ? 0 : 1;
}

// ---------------- main fused kernel ----------------
__global__ void __launch_bounds__(256, 2)
captioner_kernel(const float* __restrict__ X,      // [B, N, D]
                 const void*  __restrict__ tok,    // [B, L] i64 or i32
                 const float* __restrict__ E,      // [V, D]
                 float* __restrict__ out)
{
    // double-buffered bf16 tiles, SW128-swizzled
    __shared__ __align__(1024) uint8_t sA[2][TILE_M * 128];   // 2 x 8 KB
    __shared__ __align__(1024) uint8_t sB[2][L_DIM * 128];    // 2 x 16 KB
    __shared__ float x2s[TILE_M];
    __shared__ float y2s[L_DIM];
    __shared__ float minw[TILE_M][4];
    __shared__ long long toks[L_DIM];
    __shared__ float wsum[2];

    const int tid  = threadIdx.x;
    const int wid  = tid >> 5;
    const int lid  = tid & 31;
    const int b    = blockIdx.y;
    const int tile = blockIdx.x;

    // token gather
    if (tid < L_DIM) {
        long long idx;
        if (g_tok_is64) idx = ((const long long*)tok)[(size_t)b * L_DIM + tid];
        else            idx = (long long)((const int*)tok)[b * L_DIM + tid];
        toks[tid] = idx;
    }
    __syncthreads();

    // ---- loader mapping: 16 threads per row, float4 columns ----
    const int rbase = tid >> 4;      // 0..15
    const int c4    = tid & 15;      // float4 column within 64-float chunk
    float x2p[4], y2p[8];
    #pragma unroll
    for (int i = 0; i < 4; i++) x2p[i] = 0.0f;
    #pragma unroll
    for (int i = 0; i < 8; i++) y2p[i] = 0.0f;

    const float4* __restrict__ Xv = (const float4*)X;
    const float4* __restrict__ Ev = (const float4*)E;
    const size_t xrow0 = (size_t)b * N_DIM + (size_t)tile * TILE_M;

    const uint32_t sAu = smem_u32(&sA[0][0]);
    const uint32_t sBu = smem_u32(&sB[0][0]);

    // one swizzled base offset; rows 16 apart differ by 16*128 = 2048 bytes,
    // which does not touch the swizzle bits, so offsets add linearly.
    const uint32_t st0 = sw128((uint32_t)(rbase * 128 + c4 * 8));

    // ---- mma warp tiling: 2 (M) x 4 (N) warps; each warp 32x32 ----
    const int wid_m = wid & 1;           // 0..1 -> 32 rows each
    const int wid_n = wid >> 1;          // 0..3 -> 32 cols each
    const int g  = lid >> 2;             // accum row group
    const int t4 = lid & 3;
    const int lm = lid >> 3;             // ldmatrix matrix index 0..3
    const int lr = lid & 7;              // row within 8x8 matrix

    float acc[2][4][4];
    #pragma unroll
    for (int mt = 0; mt < 2; mt++)
        #pragma unroll
        for (int j = 0; j < 4; j++)
            #pragma unroll
            for (int q = 0; q < 4; q++) acc[mt][j][q] = 0.0f;

    const uint32_t aRow0 = (uint32_t)(wid_m * 32 + (lm & 1) * 8 + lr) * 128 + (lm >> 1) * 16;
    const uint32_t bRow0 = (uint32_t)(wid_n * 32 + (lm >> 1) * 8 + lr) * 128 + (lm & 1) * 16;

    // ---- pipeline: register-staged prefetch + double-buffered SMEM ----
    float4 fa[4], fb[8];

    // prologue: load chunk 0
    #pragma unroll
    for (int it = 0; it < 4; it++)
        fa[it] = __ldg(&Xv[(xrow0 + rbase + it * 16) * (D_DIM / 4) + c4]);
    #pragma unroll
    for (int it = 0; it < 8; it++)
        fb[it] = __ldg(&Ev[(size_t)toks[rbase + it * 16] * (D_DIM / 4) + c4]);

    for (int ck = 0; ck < N_CHUNKS; ck++) {
        const int buf = ck & 1;
        uint8_t* __restrict__ tA = sA[buf];
        uint8_t* __restrict__ tB = sB[buf];

        // ---- convert + swizzle-store current chunk, accumulate norms ----
        #pragma unroll
        for (int it = 0; it < 4; it++) {
            const float4 f = fa[it];
            x2p[it] += f.x * f.x + f.y * f.y + f.z * f.z + f.w * f.w;
            __nv_bfloat162 a0 = __floats2bfloat162_rn(f.x, f.y);
            __nv_bfloat162 a1 = __floats2bfloat162_rn(f.z, f.w);
            uint2 va; va.x = *(const uint32_t*)&a0; va.y = *(const uint32_t*)&a1;
            *(uint2*)(tA + st0 + it * 2048) = va;
        }
        #pragma unroll
        for (int it = 0; it < 8; it++) {
            const float4 gg = fb[it];
            y2p[it] += gg.x * gg.x + gg.y * gg.y + gg.z * gg.z + gg.w * gg.w;
            __nv_bfloat162 b0 = __floats2bfloat162_rn(gg.x, gg.y);
            __nv_bfloat162 b1 = __floats2bfloat162_rn(gg.z, gg.w);
            uint2 vb; vb.x = *(const uint32_t*)&b0; vb.y = *(const uint32_t*)&b1;
            *(uint2*)(tB + st0 + it * 2048) = vb;
        }

        // ---- issue next chunk's loads BEFORE the barrier (independent of SMEM) ----
        if (ck + 1 < N_CHUNKS) {
            const int kofs4 = (ck + 1) * (K_CHUNK / 4) + c4;
            #pragma unroll
            for (int it = 0; it < 4; it++)
                fa[it] = __ldg(&Xv[(xrow0 + rbase + it * 16) * (D_DIM / 4) + kofs4]);
            #pragma unroll
            for (int it = 0; it < 8; it++)
                fb[it] = __ldg(&Ev[(size_t)toks[rbase + it * 16] * (D_DIM / 4) + kofs4]);
        }
        __syncthreads();

        // ---- compute: 4 k-steps of 16 over this 64-wide chunk ----
        const uint32_t baseA = sAu + (uint32_t)buf * (TILE_M * 128);
        const uint32_t baseB = sBu + (uint32_t)buf * (L_DIM * 128);
        #pragma unroll
        for (int kk = 0; kk < 4; kk++) {
            const uint32_t kb = (uint32_t)kk * 32;
            uint32_t a[2][4];
            #pragma unroll
            for (int mt = 0; mt < 2; mt++) {
                uint32_t off = aRow0 + (uint32_t)mt * (16 * 128) + kb;
                ldmatrix_x4(a[mt][0], a[mt][1], a[mt][2], a[mt][3], baseA + sw128(off));
            }
            #pragma unroll
            for (int np = 0; np < 2; np++) {
                uint32_t off = bRow0 + (uint32_t)np * (16 * 128) + kb;
                uint32_t b0, b1, b2, b3;
                ldmatrix_x4(b0, b1, b2, b3, baseB + sw128(off));
                #pragma unroll
                for (int mt = 0; mt < 2; mt++) {
                    mma16816(acc[mt][2 * np],     a[mt][0], a[mt][1], a[mt][2], a[mt][3], b0, b1);
                    mma16816(acc[mt][2 * np + 1], a[mt][0], a[mt][1], a[mt][2], a[mt][3], b2, b3);
                }
            }
        }
        // no trailing sync: tile[buf] is next overwritten in iter ck+2, whose
        // stores happen after sync(ck+1), which all warps reach only after MMA(ck).
    }

    // ---- reduce per-row squared norms (16 lanes per row, same warp) ----
    #pragma unroll
    for (int it = 0; it < 8; it++) {
        float vy = y2p[it];
        float vx = (it < 4) ? x2p[it] : 0.0f;
        #pragma unroll
        for (int o = 1; o < 16; o <<= 1) {
            vx += __shfl_xor_sync(0xFFFFFFFFu, vx, o);
            vy += __shfl_xor_sync(0xFFFFFFFFu, vy, o);
        }
        if (c4 == 0) {
            y2s[rbase + it * 16] = vy;
            if (it < 4) x2s[rbase + it * 16] = vx;
        }
    }
    __syncthreads();

    // ---- epilogue: q = y2[col] - 2*S, min over cols ----
    float minq[2][2];
    minq[0][0] = minq[0][1] = minq[1][0] = minq[1][1] = 3.4e38f;
    #pragma unroll
    for (int mt = 0; mt < 2; mt++) {
        #pragma unroll
        for (int j = 0; j < 4; j++) {
            const int col = wid_n * 32 + j * 8 + t4 * 2;
            const float y0 = y2s[col], y1 = y2s[col + 1];
            minq[mt][0] = fminf(minq[mt][0],
                                fminf(y0 - 2.0f * acc[mt][j][0], y1 - 2.0f * acc[mt][j][1]));
            minq[mt][1] = fminf(minq[mt][1],
                                fminf(y0 - 2.0f * acc[mt][j][2], y1 - 2.0f * acc[mt][j][3]));
        }
    }
    #pragma unroll
    for (int mt = 0; mt < 2; mt++) {
        #pragma unroll
        for (int h = 0; h < 2; h++) {
            float v = minq[mt][h];
            v = fminf(v, __shfl_xor_sync(0xFFFFFFFFu, v, 1));
            v = fminf(v, __shfl_xor_sync(0xFFFFFFFFu, v, 2));
            minq[mt][h] = v;
        }
    }
    if (t4 == 0) {
        #pragma unroll
        for (int mt = 0; mt < 2; mt++) {
            const int r = wid_m * 32 + mt * 16 + g;
            minw[r][wid_n]     = minq[mt][0];
            minw[r + 8][wid_n] = minq[mt][1];
        }
    }
    __syncthreads();

    // combine the four warp-column quarters, sqrt, sum (threads 0..63 = warps 0,1)
    float dist = 0.0f;
    if (tid < TILE_M) {
        const float m = fminf(fminf(minw[tid][0], minw[tid][1]),
                              fminf(minw[tid][2], minw[tid][3]));
        dist = sqrtf(fmaxf(x2s[tid] + m, 0.0f));
    }
    #pragma unroll
    for (int o = 16; o >= 1; o >>= 1)
        dist += __shfl_xor_sync(0xFFFFFFFFu, dist, o);
    if (lid == 0 && wid < 2) wsum[wid] = dist;
    __syncthreads();

    if (tid == 0) {
        float s = (wsum[0] + wsum[1]) * (1.0f / ((float)B_DIM * (float)N_DIM));
        atomicAdd(out, s);
    }
}

// ---------------- launch ----------------
extern "C" void kernel_launch(void* const* d_in, const int* in_sizes, int n_in,
                              void* d_out, int out_size) {
    const float* X   = (const float*)d_in[0];
    const void*  tok = d_in[1];
    const float* E   = (const float*)d_in[2];
    float* out = (float*)d_out;

    prep_kernel<<<1, 256>>>((const uint2*)tok, out);
    dim3 grid(N_DIM / TILE_M, B_DIM);   // (32, 32)
    captioner_kernel<<<grid, 256>>>(X, tok, E, out);
}